// round 1
// baseline (speedup 1.0000x reference)
#include <cuda_runtime.h>
#include <cuda_bf16.h>
#include <cstdint>

// Problem constants
#define IN_CH   256
#define HW      32
#define BATCH   8
#define KF      2304            // K*K*IN_CH = 9*256
#define NOUT    512
#define L2D     1024            // 32*32
#define MROWS   (BATCH * L2D)   // 8192

// Scratch (allocation-free rule: __device__ globals)
__device__ float g_U[BATCH * KF * L2D];     // im2col, (B, 2304, 1024) contiguous == A (8192, 2304)
__device__ float g_Beff[KF * NOUT];         // expanded circulant weight, k-major, co contiguous

// ---------------------------------------------------------------------------
// Kernel 1: im2col.  U[b][f=ci*9+di*3+dj][l=h*32+w] = x[b][ci][h+di-1][w+dj-1] (0 if OOB)
// ---------------------------------------------------------------------------
__global__ void im2col_kernel(const float* __restrict__ x) {
    int idx = blockIdx.x * 256 + threadIdx.x;            // < 8*2304*1024 (exact grid)
    int l  = idx & (L2D - 1);
    int bf = idx >> 10;
    int f  = bf % KF;
    int b  = bf / KF;
    int ci = f / 9;
    int dd = f - ci * 9;
    int di = dd / 3;
    int dj = dd - di * 3;
    int h = l >> 5, w = l & 31;
    int y  = h + di - 1;
    int xw = w + dj - 1;
    float v = 0.0f;
    if ((unsigned)y < 32u && (unsigned)xw < 32u)
        v = x[((b * IN_CH + ci) << 10) + (y << 5) + xw];
    g_U[idx] = v;
}

// ---------------------------------------------------------------------------
// Kernel 2: circulant weight expansion.
// Beff[k=q*64+m][co=p*64+j] = w[p][q][(j-m) & 63]
// ---------------------------------------------------------------------------
__global__ void beff_kernel(const float* __restrict__ wgt) {
    int idx = blockIdx.x * 256 + threadIdx.x;            // < 2304*512 (exact grid)
    int co = idx & (NOUT - 1);
    int k  = idx >> 9;
    int q = k >> 6, m = k & 63;
    int p = co >> 6, j = co & 63;
    g_Beff[idx] = wgt[((p * 36 + q) << 6) + ((j - m) & 63)];
}

// ---------------------------------------------------------------------------
// Kernel 3: GEMM C[8192,512] = A @ Beff, fused transpose store to (8,512,32,32).
// 128x128 tile, BK=16, 256 threads, 8x8 per thread, packed fma.rn.f32x2.
// ---------------------------------------------------------------------------
#define BM 128
#define BN 128
#define BK 16
#define ASTRIDE 129   // pad to kill 4-way STS conflicts on transposed store

__device__ __forceinline__ unsigned long long pack2(float lo, float hi) {
    unsigned long long r;
    asm("mov.b64 %0, {%1, %2};" : "=l"(r) : "f"(lo), "f"(hi));
    return r;
}
__device__ __forceinline__ void unpack2(unsigned long long v, float& lo, float& hi) {
    asm("mov.b64 {%0, %1}, %2;" : "=f"(lo), "=f"(hi) : "l"(v));
}
__device__ __forceinline__ void ffma2(unsigned long long& d, unsigned long long a,
                                      unsigned long long b) {
    asm("fma.rn.f32x2 %0, %1, %2, %0;" : "+l"(d) : "l"(a), "l"(b));
}

__global__ void __launch_bounds__(256, 2) gemm_kernel(float* __restrict__ out) {
    __shared__ float As[BK][ASTRIDE];   // [k][m], padded
    __shared__ float Bs[BK][BN];        // [k][n]

    const int tid = threadIdx.x;
    const int tm = tid & 15;            // m sub-index (lane-adjacent => coalesced stores)
    const int tn = tid >> 4;            // n sub-index (0..15)
    const int bm = blockIdx.y * BM;
    const int bn = blockIdx.x * BN;

    unsigned long long acc[8][4];       // 8 m-values x 4 f32x2 pairs (8 n-values)
    #pragma unroll
    for (int i = 0; i < 8; i++)
        #pragma unroll
        for (int j = 0; j < 4; j++) acc[i][j] = 0ull;

    for (int k0 = 0; k0 < KF; k0 += BK) {
        // ---- load A tile: 128 rows x 16 k, float4 along k, store transposed
        #pragma unroll
        for (int s = 0; s < 2; s++) {
            int id = tid + 256 * s;
            int m  = id >> 2;
            int kk = (id & 3) << 2;
            const float4 v = *(const float4*)&g_U[(bm + m) * KF + k0 + kk];
            As[kk + 0][m] = v.x;
            As[kk + 1][m] = v.y;
            As[kk + 2][m] = v.z;
            As[kk + 3][m] = v.w;
        }
        // ---- load B tile: 16 k x 128 n, float4 along n
        #pragma unroll
        for (int s = 0; s < 2; s++) {
            int id = tid + 256 * s;
            int kk = id >> 5;
            int n  = (id & 31) << 2;
            *(float4*)&Bs[kk][n] = *(const float4*)&g_Beff[(k0 + kk) * NOUT + bn + n];
        }
        __syncthreads();

        #pragma unroll
        for (int kk = 0; kk < BK; kk++) {
            float a[8];
            #pragma unroll
            for (int i = 0; i < 8; i++) a[i] = As[kk][tm + 16 * i];
            const float4 b0 = *(const float4*)&Bs[kk][tn * 8];
            const float4 b1 = *(const float4*)&Bs[kk][tn * 8 + 4];
            unsigned long long bp[4];
            bp[0] = pack2(b0.x, b0.y);
            bp[1] = pack2(b0.z, b0.w);
            bp[2] = pack2(b1.x, b1.y);
            bp[3] = pack2(b1.z, b1.w);
            #pragma unroll
            for (int i = 0; i < 8; i++) {
                const unsigned long long a2 = pack2(a[i], a[i]);
                ffma2(acc[i][0], a2, bp[0]);
                ffma2(acc[i][1], a2, bp[1]);
                ffma2(acc[i][2], a2, bp[2]);
                ffma2(acc[i][3], a2, bp[3]);
            }
        }
        __syncthreads();
    }

    // ---- epilogue: C[r][co] -> out[b][co][l2], r = b*1024 + l2
    #pragma unroll
    for (int i = 0; i < 8; i++) {
        const int r  = bm + tm + 16 * i;
        const int b  = r >> 10;
        const int l2 = r & (L2D - 1);
        float* orow = out + ((b * NOUT) << 10) + l2;
        #pragma unroll
        for (int jj = 0; jj < 4; jj++) {
            float lo, hi;
            unpack2(acc[i][jj], lo, hi);
            const int co = bn + tn * 8 + 2 * jj;
            orow[co << 10]       = lo;
            orow[(co + 1) << 10] = hi;
        }
    }
}

// ---------------------------------------------------------------------------
extern "C" void kernel_launch(void* const* d_in, const int* in_sizes, int n_in,
                              void* d_out, int out_size) {
    const float* x = (const float*)d_in[0];
    const float* w = (const float*)d_in[1];
    // defensive: identify by size (x = 2,097,152; weight = 18,432)
    if (n_in >= 2 && in_sizes[0] == 8 * 36 * 64) {
        const float* t = x; x = w; w = t;
    }
    float* out = (float*)d_out;

    im2col_kernel<<<(BATCH * KF * L2D) / 256, 256>>>(x);
    beff_kernel<<<(KF * NOUT) / 256, 256>>>(w);
    gemm_kernel<<<dim3(NOUT / BN, MROWS / BM), 256>>>(out);
    (void)out_size;
}

// round 3
// speedup vs baseline: 3.9953x; 3.9953x over previous
#include <cuda_runtime.h>
#include <cuda_bf16.h>
#include <cstdint>

// ---------------- problem constants ----------------
#define IN_CH   256
#define BATCH   8
#define KF      2304            // 9*256
#define NOUT    512
#define L2D     1024
#define MROWS   (BATCH * L2D)   // 8192

// GEMM tiling
#define BK   32                 // k per chunk (4 mma k-atoms of 8)
#define NS   3                  // cp.async pipeline stages
#define NCH  (KF / BK)          // 72
#define TSZ  (128 * BK * 4)     // 16KB per operand tile
#define STAGE (2 * TSZ)         // 32KB
#define SMEM_TOTAL (NS * STAGE) // 96KB

// scratch (__device__ globals: allocation-free rule)
// g_U is the im2col buffer in [b][f][l] order; A rows are FLAT 2304-elem slices
// of it (matches reference's reshape(-1, Q, BLOCK) reinterpretation).
__device__ float g_U[(size_t)MROWS * KF];
__device__ float g_BeffT[(size_t)NOUT * KF];   // B^T: [co][k]

// ---------------- helpers ----------------
__device__ __forceinline__ float to_tf32(float v) {
    float r; asm("cvt.rna.tf32.f32 %0, %1;" : "=f"(r) : "f"(v)); return r;
}
__device__ __forceinline__ void cpa16(uint32_t dst, const void* src) {
    asm volatile("cp.async.cg.shared.global [%0], [%1], 16;" :: "r"(dst), "l"(src));
}
#define CP_COMMIT() asm volatile("cp.async.commit_group;" ::: "memory")
#define CP_WAIT1()  asm volatile("cp.async.wait_group 1;" ::: "memory")

// swizzled smem tile: addr(row, k) = row*128 + ((k/4 ^ row%8)*16) + (k%4)*4
__device__ __forceinline__ uint32_t lds32(const char* base, int row, int k) {
    return *(const uint32_t*)(base + row * 128 + (((k >> 2) ^ (row & 7)) << 4) + ((k & 3) << 2));
}
__device__ __forceinline__ void mma8(float* c, const uint32_t* a, const uint32_t* b) {
    asm volatile(
        "mma.sync.aligned.m16n8k8.row.col.f32.tf32.tf32.f32 "
        "{%0,%1,%2,%3}, {%4,%5,%6,%7}, {%8,%9}, {%0,%1,%2,%3};"
        : "+f"(c[0]), "+f"(c[1]), "+f"(c[2]), "+f"(c[3])
        : "r"(a[0]), "r"(a[1]), "r"(a[2]), "r"(a[3]), "r"(b[0]), "r"(b[1]));
}

// ---------------------------------------------------------------------------
// Kernel 1: im2col -> g_U[b][f][l] (flat), tf32-rounded. grid (9, 256, 8).
// ---------------------------------------------------------------------------
__global__ void im2col_kernel(const float* __restrict__ x) {
    const int dd = blockIdx.x, ci = blockIdx.y, b = blockIdx.z;
    const int oy = dd / 3 - 1, ox = dd % 3 - 1;      // uniform per block
    const float* xp = x + (((size_t)(b * IN_CH + ci)) << 10);
    float* up = g_U + (((size_t)(b * KF + ci * 9 + dd)) << 10);
    #pragma unroll
    for (int s = 0; s < 4; s++) {
        int l = threadIdx.x + s * 256;
        int h = l >> 5, w = l & 31;
        int y = h + oy, xw = w + ox;
        float v = 0.0f;
        if ((unsigned)y < 32u && (unsigned)xw < 32u) v = xp[(y << 5) + xw];
        up[l] = to_tf32(v);
    }
}

// ---------------------------------------------------------------------------
// Kernel 2: B^T expansion, tf32-rounded. BeffT[co][k] = w[p][q][(j-m)&63]
// ---------------------------------------------------------------------------
__global__ void beffT_kernel(const float* __restrict__ wgt) {
    const int co = blockIdx.y;
    const int k = blockIdx.x * 256 + threadIdx.x;
    const int q = k >> 6, m = k & 63;
    const int p = co >> 6, j = co & 63;
    g_BeffT[(size_t)co * KF + k] = to_tf32(wgt[((p * 36 + q) << 6) + ((j - m) & 63)]);
}

// ---------------------------------------------------------------------------
// Kernel 3: tf32 mma.sync GEMM C[8192,512] = A @ B, fused transpose store.
// CTA 128x128, 8 warps (2m x 4n), warp tile 64x32, 3-stage cp.async.
// ---------------------------------------------------------------------------
__global__ void __launch_bounds__(256, 2) gemm_kernel(float* __restrict__ out) {
    extern __shared__ char sm[];
    const int tid = threadIdx.x;
    const int lane = tid & 31;
    const int wid = tid >> 5;
    const int g = lane >> 2, t = lane & 3;
    const int wm = wid >> 2, wn = wid & 3;
    const int bm = blockIdx.y * 128;
    const int bn = blockIdx.x * 128;

    float acc[4][4][4];
    #pragma unroll
    for (int i = 0; i < 4; i++)
        #pragma unroll
        for (int j = 0; j < 4; j++)
            #pragma unroll
            for (int q = 0; q < 4; q++) acc[i][j][q] = 0.0f;

    auto load_chunk = [&](int c, int s) {
        char* As = sm + s * STAGE;
        char* Bs = As + TSZ;
        const int k0 = c * BK;
        #pragma unroll
        for (int i = 0; i < 4; i++) {
            int id = tid + i * 256;
            int row = id >> 3, cj = id & 7;
            uint32_t swo = (uint32_t)(row * 128 + ((cj ^ (row & 7)) << 4));
            cpa16((uint32_t)__cvta_generic_to_shared(As + swo),
                  &g_U[(size_t)(bm + row) * KF + k0 + cj * 4]);
            cpa16((uint32_t)__cvta_generic_to_shared(Bs + swo),
                  &g_BeffT[(size_t)(bn + row) * KF + k0 + cj * 4]);
        }
    };

    auto compute = [&](int s) {
        const char* As = sm + s * STAGE;
        const char* Bs = As + TSZ;
        #pragma unroll
        for (int kk = 0; kk < 4; kk++) {
            const int k0 = kk * 8;
            uint32_t a[4][4], b[4][2];
            #pragma unroll
            for (int ma = 0; ma < 4; ma++) {
                int r0 = wm * 64 + ma * 16 + g;
                a[ma][0] = lds32(As, r0,     k0 + t);
                a[ma][1] = lds32(As, r0 + 8, k0 + t);
                a[ma][2] = lds32(As, r0,     k0 + t + 4);
                a[ma][3] = lds32(As, r0 + 8, k0 + t + 4);
            }
            #pragma unroll
            for (int na = 0; na < 4; na++) {
                int n0 = wn * 32 + na * 8 + g;
                b[na][0] = lds32(Bs, n0, k0 + t);
                b[na][1] = lds32(Bs, n0, k0 + t + 4);
            }
            #pragma unroll
            for (int ma = 0; ma < 4; ma++)
                #pragma unroll
                for (int na = 0; na < 4; na++)
                    mma8(acc[ma][na], a[ma], b[na]);
        }
    };

    // prologue: prefetch NS-1 chunks
    #pragma unroll
    for (int s = 0; s < NS - 1; s++) { load_chunk(s, s); CP_COMMIT(); }

    for (int c = 0; c < NCH; c++) {
        CP_WAIT1();
        __syncthreads();
        const int cn = c + NS - 1;
        if (cn < NCH) { load_chunk(cn, cn % NS); CP_COMMIT(); }
        compute(c % NS);
    }

    // epilogue: C[r][co] -> out[b][co][l2], r = b*1024 + l2
    #pragma unroll
    for (int ma = 0; ma < 4; ma++) {
        #pragma unroll
        for (int half = 0; half < 2; half++) {
            const int r = bm + wm * 64 + ma * 16 + g + half * 8;
            const int b = r >> 10;
            const int l2 = r & (L2D - 1);
            float* op = out + (((size_t)b * NOUT) << 10) + l2;
            #pragma unroll
            for (int na = 0; na < 4; na++) {
                const int co = bn + wn * 32 + na * 8 + t * 2;
                op[(size_t)co << 10]       = acc[ma][na][half * 2 + 0];
                op[(size_t)(co + 1) << 10] = acc[ma][na][half * 2 + 1];
            }
        }
    }
}

// ---------------------------------------------------------------------------
extern "C" void kernel_launch(void* const* d_in, const int* in_sizes, int n_in,
                              void* d_out, int out_size) {
    const float* x = (const float*)d_in[0];
    const float* w = (const float*)d_in[1];
    if (n_in >= 2 && in_sizes[0] == 8 * 36 * 64) {   // defensive swap by size
        const float* tp = x; x = w; w = tp;
    }
    float* out = (float*)d_out;

    cudaFuncSetAttribute(gemm_kernel, cudaFuncAttributeMaxDynamicSharedMemorySize, SMEM_TOTAL);

    im2col_kernel<<<dim3(9, IN_CH, BATCH), 256>>>(x);
    beffT_kernel<<<dim3(KF / 256, NOUT), 256>>>(w);
    gemm_kernel<<<dim3(NOUT / 128, MROWS / 128), 256, SMEM_TOTAL>>>(out);
    (void)out_size;
}